// round 10
// baseline (speedup 1.0000x reference)
#include <cuda_runtime.h>
#include <cstdint>

// FasterPConv via portable mma.sync m16n8k8 tf32, single-pass tf32 precision.
// B=2, N=80000, K=16, C=32, H=4, M=8.
// Per point: out[32c x 8m] = gf^T(32x16) * w(16x8), one warp per point.
// gf[k][c] = feat[b, idx[k], c] * guid[k, c>>3], rounded to tf32 at gather time.
// R10: neighbor indices via warp-uniform broadcast LDG.128 (4 wf total) instead
// of lane-held LDG + 16 SHFL broadcasts (17 wf). int4 fields used directly as
// scalars (no indexable array -> no local-memory spill risk).

#define NPERB 80000
#define FULLMASK 0xffffffffu

__device__ __forceinline__ uint32_t tf32_rn(float v) {
    uint32_t u;
    asm("cvt.rna.tf32.f32 %0, %1;" : "=r"(u) : "f"(v));
    return u;
}

__device__ __forceinline__ void mma8(float d[4], const uint32_t a[4],
                                     uint32_t b0, uint32_t b1) {
    asm volatile(
        "mma.sync.aligned.m16n8k8.row.col.f32.tf32.tf32.f32 "
        "{%0,%1,%2,%3}, {%4,%5,%6,%7}, {%8,%9}, {%0,%1,%2,%3};"
        : "+f"(d[0]), "+f"(d[1]), "+f"(d[2]), "+f"(d[3])
        : "r"(a[0]), "r"(a[1]), "r"(a[2]), "r"(a[3]), "r"(b0), "r"(b1));
}

__global__ void __launch_bounds__(256)
pconv_hmma(const float* __restrict__ feat, const int* __restrict__ inds,
           const float* __restrict__ guid, const float* __restrict__ wn,
           float* __restrict__ out) {
    // Per-warp staging. Row stride 40 words (40 mod 32 = 8): bank = (8k + c) & 31,
    // bijective over every fragment's 32 lanes -> conflict-free STS and LDS.
    // Reused (stride 36) for the D transpose before the coalesced store.
    __shared__ uint32_t s_gf[8][16 * 40];

    const int warp = threadIdx.x >> 5;
    const int lane = threadIdx.x & 31;
    const int point = blockIdx.x * 8 + warp;       // grid covers 160000 exactly
    uint32_t* sg = s_gf[warp];

    // ---- neighbor indices: warp-uniform broadcast LDG.128 x4 (1 wf each) ----
    const int4* ip = (const int4*)(inds + (size_t)point * 16);
    const int4 i0 = __ldg(ip + 0);
    const int4 i1 = __ldg(ip + 1);
    const int4 i2 = __ldg(ip + 2);
    const int4 i3 = __ldg(ip + 3);

    // ---- B operand loads issued early (raises MLP; used after gather) ----
    // b(q,j): k = (lane&3) + 4j + 8q, m = lane>>2.
    // Word index 8*(lane&3) + (lane>>2) + 32j + 64q: each LDG covers one
    // permuted-but-contiguous 128B line -> coalesced.
    const float* wp = wn + (size_t)point * 128;
    const int widx = 8 * (lane & 3) + (lane >> 2);
    float wraw[2][2];
    #pragma unroll
    for (int q = 0; q < 2; q++)
        #pragma unroll
        for (int j = 0; j < 2; j++)
            wraw[q][j] = __ldg(wp + widx + 32 * j + 64 * q);

    // ---- guidance, coalesced: lane j holds guid[point*64 + j] ----
    const float g0 = __ldg(guid + point * 64 + lane);
    const float g1 = __ldg(guid + point * 64 + 32 + lane);
    const int h = lane >> 3;                        // head of this lane's channel

    const float* fb = feat + ((point >= NPERB) ? NPERB * 32 : 0);

    // ---- gather + guidance multiply + tf32 round + stage gf[k][c] ----
    // Four explicit 4-k chunks; int4 fields consumed as scalars.
#define GF_ONE(kconst, idx, gsrc, goff)                                        \
    do {                                                                       \
        const float fv = __ldg(fb + (idx) * 32 + lane);                        \
        const float gv = __shfl_sync(FULLMASK, (gsrc), (goff) * 4 + h);        \
        sg[(kconst) * 40 + lane] = tf32_rn(fv * gv);                           \
    } while (0)

    GF_ONE( 0, i0.x, g0, 0);  GF_ONE( 1, i0.y, g0, 1);
    GF_ONE( 2, i0.z, g0, 2);  GF_ONE( 3, i0.w, g0, 3);
    GF_ONE( 4, i1.x, g0, 4);  GF_ONE( 5, i1.y, g0, 5);
    GF_ONE( 6, i1.z, g0, 6);  GF_ONE( 7, i1.w, g0, 7);
    GF_ONE( 8, i2.x, g1, 0);  GF_ONE( 9, i2.y, g1, 1);
    GF_ONE(10, i2.z, g1, 2);  GF_ONE(11, i2.w, g1, 3);
    GF_ONE(12, i3.x, g1, 4);  GF_ONE(13, i3.y, g1, 5);
    GF_ONE(14, i3.z, g1, 6);  GF_ONE(15, i3.w, g1, 7);
#undef GF_ONE
    __syncwarp();

    // ---- B fragments: tf32 round only (single-pass precision) ----
    uint32_t B[2][2];
    #pragma unroll
    for (int q = 0; q < 2; q++)
        #pragma unroll
        for (int j = 0; j < 2; j++)
            B[q][j] = tf32_rn(wraw[q][j]);

    float d[2][4];
    #pragma unroll
    for (int t = 0; t < 2; t++)
        #pragma unroll
        for (int i = 0; i < 4; i++) d[t][i] = 0.0f;

    // ---- 2 M-tiles x 2 K-halves ----
    #pragma unroll
    for (int t = 0; t < 2; t++) {
        #pragma unroll
        for (int q = 0; q < 2; q++) {
            uint32_t A[4];
            #pragma unroll
            for (int i = 0; i < 4; i++) {
                const int k = (lane & 3) + 4 * (i >> 1) + 8 * q;
                const int c = (lane >> 2) + 8 * (i & 1) + 16 * t;
                A[i] = sg[k * 40 + c];
            }
            mma8(d[t], A, B[q][0], B[q][1]);
        }
    }
    __syncwarp();   // all A-frag reads complete before sg is overwritten

    // ---- D -> smem transpose (stride 36: bank = (4m + c)&31, conflict-free) ----
    // d[t][i]: m = (lane&3)*2 + (i&1), c = (lane>>2) + 8*(i>>1) + 16*t.
    #pragma unroll
    for (int t = 0; t < 2; t++)
        #pragma unroll
        for (int i = 0; i < 4; i++) {
            const int m = (lane & 3) * 2 + (i & 1);
            const int c = (lane >> 2) + 8 * (i >> 1) + 16 * t;
            sg[m * 36 + c] = __float_as_uint(d[t][i]);
        }
    __syncwarp();

    // ---- coalesced store: out[point, m*32 + c] ----
    float* op = out + (size_t)point * 256;
    #pragma unroll
    for (int m = 0; m < 8; m++)
        op[m * 32 + lane] = __uint_as_float(sg[m * 36 + lane]);
}

extern "C" void kernel_launch(void* const* d_in, const int* in_sizes, int n_in,
                              void* d_out, int out_size) {
    const float* feat = (const float*)d_in[0];   // [B,N,C]
    const int*   inds = (const int*)  d_in[1];   // [B,N,K]
    const float* guid = (const float*)d_in[2];   // [B,N,K,H]
    const float* wn   = (const float*)d_in[3];   // [B,N,K,M]
    float* out = (float*)d_out;                  // [B,N,M*C]

    pconv_hmma<<<20000, 256>>>(feat, inds, guid, wn, out);
}

// round 12
// speedup vs baseline: 1.0715x; 1.0715x over previous
#include <cuda_runtime.h>
#include <cuda_fp16.h>
#include <cstdint>

// FasterPConv via mma.sync m16n8k16 f16 (f32 accumulate).
// B=2, N=80000, K=16, C=32, H=4, M=8.
// Per point: out[32c x 8m] = gf^T(32x16) * w(16x8), one warp per point.
// gf[k][c] = feat[b, idx[k], c] * guid[k, c>>3], rounded to f16 (10-bit mantissa,
// same as tf32; measured tf32 rel_err 2.9e-4 << 1e-3).
// fp16 packing halves the gf smem round-trip (2KB -> 1KB per point) and cuts
// MMA count 4 -> 2 (K=16 in one step).

#define NPERB 80000
#define FULLMASK 0xffffffffu

__device__ __forceinline__ uint32_t pack_f16x2(float lo, float hi) {
    // d[15:0] = lo, d[31:16] = hi  (PTX: cvt.rn.f16x2.f32 d, a, b -> hi=a, lo=b)
    uint32_t d;
    asm("cvt.rn.f16x2.f32 %0, %1, %2;" : "=r"(d) : "f"(hi), "f"(lo));
    return d;
}

__device__ __forceinline__ void mma16(float d[4], const uint32_t a[4],
                                      uint32_t b0, uint32_t b1) {
    asm volatile(
        "mma.sync.aligned.m16n8k16.row.col.f32.f16.f16.f32 "
        "{%0,%1,%2,%3}, {%4,%5,%6,%7}, {%8,%9}, {%0,%1,%2,%3};"
        : "+f"(d[0]), "+f"(d[1]), "+f"(d[2]), "+f"(d[3])
        : "r"(a[0]), "r"(a[1]), "r"(a[2]), "r"(a[3]), "r"(b0), "r"(b1));
}

__global__ void __launch_bounds__(256)
pconv_hmma(const float* __restrict__ feat, const int* __restrict__ inds,
           const float* __restrict__ guid, const float* __restrict__ wn,
           float* __restrict__ out) {
    // Per-warp staging: 8 k-pair rows x 32 c of f16x2, stride 40
    // (bank = (8j + c) & 31, bijective per access group -> conflict-free).
    // Reused (stride 36 words) for the f32 D transpose (8m x 32c fits: 288 < 320).
    __shared__ uint32_t s_gf[8][8 * 40];

    const int warp = threadIdx.x >> 5;
    const int lane = threadIdx.x & 31;
    const int point = blockIdx.x * 8 + warp;       // grid covers 160000 exactly
    uint32_t* sg = s_gf[warp];

    // ---- neighbor indices: warp-uniform broadcast LDG.128 x4 ----
    const int4* ip = (const int4*)(inds + (size_t)point * 16);
    const int4 i0 = __ldg(ip + 0);
    const int4 i1 = __ldg(ip + 1);
    const int4 i2 = __ldg(ip + 2);
    const int4 i3 = __ldg(ip + 3);

    // ---- B operand (weights) loads issued early ----
    // b0 needs w[k=2(lane&3)][m=lane>>2] and k+1; b1 needs k+8, k+9.
    // word(k,m) = 8k + m  ->  base = 16(lane&3) + (lane>>2).
    const float* wp = wn + (size_t)point * 128;
    const int wbase = 16 * (lane & 3) + (lane >> 2);
    const float w0 = __ldg(wp + wbase);
    const float w1 = __ldg(wp + wbase + 8);
    const float w2 = __ldg(wp + wbase + 64);
    const float w3 = __ldg(wp + wbase + 72);

    // ---- guidance, coalesced: lane j holds guid[point*64 + j] ----
    const float g0 = __ldg(guid + point * 64 + lane);
    const float g1 = __ldg(guid + point * 64 + 32 + lane);
    const int h = lane >> 3;                        // head of this lane's channel

    const float* fb = feat + ((point >= NPERB) ? NPERB * 32 : 0);

    // ---- gather + guidance multiply + f16 pack + stage: sg[j][c] holds
    //      half2(gf[2j][c], gf[2j+1][c]) ----
#define GF_PAIR(j, idxA, idxB, gsrc, ga, gb)                                   \
    do {                                                                       \
        const float fa = __ldg(fb + (idxA) * 32 + lane);                       \
        const float fbv = __ldg(fb + (idxB) * 32 + lane);                      \
        const float gva = __shfl_sync(FULLMASK, (gsrc), (ga) * 4 + h);         \
        const float gvb = __shfl_sync(FULLMASK, (gsrc), (gb) * 4 + h);         \
        sg[(j) * 40 + lane] = pack_f16x2(fa * gva, fbv * gvb);                 \
    } while (0)

    GF_PAIR(0, i0.x, i0.y, g0, 0, 1);
    GF_PAIR(1, i0.z, i0.w, g0, 2, 3);
    GF_PAIR(2, i1.x, i1.y, g0, 4, 5);
    GF_PAIR(3, i1.z, i1.w, g0, 6, 7);
    GF_PAIR(4, i2.x, i2.y, g1, 0, 1);
    GF_PAIR(5, i2.z, i2.w, g1, 2, 3);
    GF_PAIR(6, i3.x, i3.y, g1, 4, 5);
    GF_PAIR(7, i3.z, i3.w, g1, 6, 7);
#undef GF_PAIR
    __syncwarp();

    // ---- B fragments: pack 4 f32 weights into 2 f16x2 regs ----
    const uint32_t B0 = pack_f16x2(w0, w1);   // k = 2(lane&3), +1
    const uint32_t B1 = pack_f16x2(w2, w3);   // k = 2(lane&3)+8, +9

    // ---- 2 M-tiles (t = c-halves), K=16 in one mma each ----
    float d[2][4];
    #pragma unroll
    for (int t = 0; t < 2; t++) {
        #pragma unroll
        for (int i = 0; i < 4; i++) d[t][i] = 0.0f;
        // A frags: a0:(c=lane>>2, j=lane&3)  a1:(c+8)  a2:(j+4)  a3:(c+8, j+4)
        uint32_t A[4];
        const int c0 = (lane >> 2) + 16 * t;
        const int j0 = (lane & 3);
        A[0] = sg[j0 * 40 + c0];
        A[1] = sg[j0 * 40 + c0 + 8];
        A[2] = sg[(j0 + 4) * 40 + c0];
        A[3] = sg[(j0 + 4) * 40 + c0 + 8];
        mma16(d[t], A, B0, B1);
    }
    __syncwarp();   // all A-frag reads complete before sg is overwritten

    // ---- D -> smem transpose (stride 36: bank = (8m' + c)&31, conflict-free) ----
    // d[t]: d0:(c=lane>>2+16t, m=2(lane&3))  d1:m+1  d2:(c+8, m)  d3:(c+8, m+1)
    #pragma unroll
    for (int t = 0; t < 2; t++) {
        const int c0 = (lane >> 2) + 16 * t;
        const int m0 = 2 * (lane & 3);
        sg[m0 * 36 + c0]            = __float_as_uint(d[t][0]);
        sg[(m0 + 1) * 36 + c0]      = __float_as_uint(d[t][1]);
        sg[m0 * 36 + c0 + 8]        = __float_as_uint(d[t][2]);
        sg[(m0 + 1) * 36 + c0 + 8]  = __float_as_uint(d[t][3]);
    }
    __syncwarp();

    // ---- coalesced store: out[point, m*32 + c] ----
    float* op = out + (size_t)point * 256;
    #pragma unroll
    for (int m = 0; m < 8; m++)
        op[m * 32 + lane] = __uint_as_float(sg[m * 36 + lane]);
}

extern "C" void kernel_launch(void* const* d_in, const int* in_sizes, int n_in,
                              void* d_out, int out_size) {
    const float* feat = (const float*)d_in[0];   // [B,N,C]
    const int*   inds = (const int*)  d_in[1];   // [B,N,K]
    const float* guid = (const float*)d_in[2];   // [B,N,K,H]
    const float* wn   = (const float*)d_in[3];   // [B,N,K,M]
    float* out = (float*)d_out;                  // [B,N,M*C]

    pconv_hmma<<<20000, 256>>>(feat, inds, guid, wn, out);
}

// round 13
// speedup vs baseline: 1.1246x; 1.0496x over previous
#include <cuda_runtime.h>
#include <cuda_fp16.h>
#include <cstdint>

// FasterPConv via mma.sync m16n8k16 f16 (f32 accumulate).
// B=2, N=80000, K=16, C=32, H=4, M=8.
// Per point: out[32c x 8m] = gf^T(32x16) * w(16x8), one warp per point.
// R13: (1) D fragments stored directly to GMEM (no smem D transpose):
//      24 -> ~16 MIO wf. (2) guidance broadcast halved via pre-packed f16x2
//      (g[2j],g[2j+1]) pairs: 16 -> 10 wf. f32 multiply kept (g gets one
//      extra f16 rounding; predicted rel_err ~4.5e-4 < 1e-3).

#define NPERB 80000
#define FULLMASK 0xffffffffu

__device__ __forceinline__ uint32_t pack_f16x2(float lo, float hi) {
    // d[15:0] = lo, d[31:16] = hi  (cvt.rn.f16x2.f32 d, a, b -> hi=a, lo=b)
    uint32_t d;
    asm("cvt.rn.f16x2.f32 %0, %1, %2;" : "=r"(d) : "f"(hi), "f"(lo));
    return d;
}

__device__ __forceinline__ float2 unpack_f16x2(uint32_t p) {
    const __half2 h = *reinterpret_cast<const __half2*>(&p);
    return __half22float2(h);       // exact f16 -> f32
}

__device__ __forceinline__ void mma16(float d[4], const uint32_t a[4],
                                      uint32_t b0, uint32_t b1) {
    asm volatile(
        "mma.sync.aligned.m16n8k16.row.col.f32.f16.f16.f32 "
        "{%0,%1,%2,%3}, {%4,%5,%6,%7}, {%8,%9}, {%0,%1,%2,%3};"
        : "+f"(d[0]), "+f"(d[1]), "+f"(d[2]), "+f"(d[3])
        : "r"(a[0]), "r"(a[1]), "r"(a[2]), "r"(a[3]), "r"(b0), "r"(b1));
}

__global__ void __launch_bounds__(256)
pconv_hmma(const float* __restrict__ feat, const int* __restrict__ inds,
           const float* __restrict__ guid, const float* __restrict__ wn,
           float* __restrict__ out) {
    // Per-warp A staging: 8 k-pair rows x 32 c of f16x2, stride 40
    // (bank = (8j + c) & 31, bijective per access group -> conflict-free).
    __shared__ uint32_t s_gf[8][8 * 40];

    const int warp = threadIdx.x >> 5;
    const int lane = threadIdx.x & 31;
    const int point = blockIdx.x * 8 + warp;       // grid covers 160000 exactly
    uint32_t* sg = s_gf[warp];

    // ---- neighbor indices: warp-uniform broadcast LDG.128 x4 ----
    const int4* ip = (const int4*)(inds + (size_t)point * 16);
    const int4 i0 = __ldg(ip + 0);
    const int4 i1 = __ldg(ip + 1);
    const int4 i2 = __ldg(ip + 2);
    const int4 i3 = __ldg(ip + 3);

    // ---- B operand (weights) loads issued early ----
    // b0: w[k=2(lane&3)][m=lane>>2], k+1; b1: k+8, k+9. word(k,m) = 8k + m.
    const float* wp = wn + (size_t)point * 128;
    const int wbase = 16 * (lane & 3) + (lane >> 2);
    const float w0 = __ldg(wp + wbase);
    const float w1 = __ldg(wp + wbase + 8);
    const float w2 = __ldg(wp + wbase + 64);
    const float w3 = __ldg(wp + wbase + 72);

    // ---- guidance, coalesced: lane j holds guid[point*64 + j] ----
    // G[k][h] = guid[4k+h]. Pre-pack P[j][h] = (G[2j][h], G[2j+1][h]) as f16x2,
    // resident at lane 8j+h (partner = lane+4, lanes with bit2=0 hold valid data).
    const float g0 = __ldg(guid + point * 64 + lane);
    const float g1 = __ldg(guid + point * 64 + 32 + lane);
    const uint32_t gpackA = pack_f16x2(g0, __shfl_xor_sync(FULLMASK, g0, 4));
    const uint32_t gpackB = pack_f16x2(g1, __shfl_xor_sync(FULLMASK, g1, 4));
    const int hsel = lane >> 3;                     // head of this lane's channel

    const float* fb = feat + ((point >= NPERB) ? NPERB * 32 : 0);

    // ---- gather + guidance multiply (f32) + f16 pack + stage:
    //      sg[j][c] = half2(gf[2j][c], gf[2j+1][c]) ----
#define GF_PAIR(j, idxA, idxB, gpack)                                          \
    do {                                                                       \
        const float fa = __ldg(fb + (idxA) * 32 + lane);                       \
        const float fbv = __ldg(fb + (idxB) * 32 + lane);                      \
        const uint32_t gp = __shfl_sync(FULLMASK, (gpack), 8 * ((j) & 3) + hsel); \
        const float2 gv = unpack_f16x2(gp);                                    \
        sg[(j) * 40 + lane] = pack_f16x2(fa * gv.x, fbv * gv.y);               \
    } while (0)

    GF_PAIR(0, i0.x, i0.y, gpackA);
    GF_PAIR(1, i0.z, i0.w, gpackA);
    GF_PAIR(2, i1.x, i1.y, gpackA);
    GF_PAIR(3, i1.z, i1.w, gpackA);
    GF_PAIR(4, i2.x, i2.y, gpackB);
    GF_PAIR(5, i2.z, i2.w, gpackB);
    GF_PAIR(6, i3.x, i3.y, gpackB);
    GF_PAIR(7, i3.z, i3.w, gpackB);
#undef GF_PAIR
    __syncwarp();

    // ---- B fragments: pack 4 f32 weights into 2 f16x2 regs ----
    const uint32_t B0 = pack_f16x2(w0, w1);   // k = 2(lane&3), +1
    const uint32_t B1 = pack_f16x2(w2, w3);   // k = 2(lane&3)+8, +9

    // ---- 2 M-tiles (t = c-halves), K=16 in one mma each; direct D store ----
    float* op = out + (size_t)point * 256;
    const int j0 = lane & 3;
    #pragma unroll
    for (int t = 0; t < 2; t++) {
        float d[4] = {0.f, 0.f, 0.f, 0.f};
        // A frags: a0:(c=c0, j=j0)  a1:(c0+8)  a2:(j0+4)  a3:(c0+8, j0+4)
        const int c0 = (lane >> 2) + 16 * t;
        uint32_t A[4];
        A[0] = sg[j0 * 40 + c0];
        A[1] = sg[j0 * 40 + c0 + 8];
        A[2] = sg[(j0 + 4) * 40 + c0];
        A[3] = sg[(j0 + 4) * 40 + c0 + 8];
        mma16(d, A, B0, B1);

        // D direct to GMEM: d0:(c0, m0=2(lane&3)) d1:(c0, m0+1)
        //                   d2:(c0+8, m0)         d3:(c0+8, m0+1)
        const int m0 = 2 * (lane & 3);
        op[m0 * 32 + c0]           = d[0];
        op[(m0 + 1) * 32 + c0]     = d[1];
        op[m0 * 32 + c0 + 8]       = d[2];
        op[(m0 + 1) * 32 + c0 + 8] = d[3];
    }
}

extern "C" void kernel_launch(void* const* d_in, const int* in_sizes, int n_in,
                              void* d_out, int out_size) {
    const float* feat = (const float*)d_in[0];   // [B,N,C]
    const int*   inds = (const int*)  d_in[1];   // [B,N,K]
    const float* guid = (const float*)d_in[2];   // [B,N,K,H]
    const float* wn   = (const float*)d_in[3];   // [B,N,K,M]
    float* out = (float*)d_out;                  // [B,N,M*C]

    pconv_hmma<<<20000, 256>>>(feat, inds, guid, wn, out);
}

// round 15
// speedup vs baseline: 1.1534x; 1.0256x over previous
#include <cuda_runtime.h>
#include <cuda_fp16.h>
#include <cstdint>

// FasterPConv via mma.sync m16n8k16 f16 (f32 accumulate).
// B=2, N=80000, K=16, C=32, H=4, M=8.
// Per point: out[32c x 8m] = gf^T(32x16) * w(16x8), one warp per point.
// R14/R15 = R13 (packed-guidance broadcast, f16 A staging, K=16 single-step MMA)
//       + restored smem D transpose (R12): scattered 4-line STG.32 (~32 wf)
//       replaced by STS/LDS/coalesced-STG (24 wf, all conflict-free).

#define NPERB 80000
#define FULLMASK 0xffffffffu

__device__ __forceinline__ uint32_t pack_f16x2(float lo, float hi) {
    // d[15:0] = lo, d[31:16] = hi  (cvt.rn.f16x2.f32 d, a, b -> hi=a, lo=b)
    uint32_t d;
    asm("cvt.rn.f16x2.f32 %0, %1, %2;" : "=r"(d) : "f"(hi), "f"(lo));
    return d;
}

__device__ __forceinline__ float2 unpack_f16x2(uint32_t p) {
    const __half2 h = *reinterpret_cast<const __half2*>(&p);
    return __half22float2(h);       // exact f16 -> f32
}

__device__ __forceinline__ void mma16(float d[4], const uint32_t a[4],
                                      uint32_t b0, uint32_t b1) {
    asm volatile(
        "mma.sync.aligned.m16n8k16.row.col.f32.f16.f16.f32 "
        "{%0,%1,%2,%3}, {%4,%5,%6,%7}, {%8,%9}, {%0,%1,%2,%3};"
        : "+f"(d[0]), "+f"(d[1]), "+f"(d[2]), "+f"(d[3])
        : "r"(a[0]), "r"(a[1]), "r"(a[2]), "r"(a[3]), "r"(b0), "r"(b1));
}

__global__ void __launch_bounds__(256)
pconv_hmma(const float* __restrict__ feat, const int* __restrict__ inds,
           const float* __restrict__ guid, const float* __restrict__ wn,
           float* __restrict__ out) {
    // Per-warp staging: 8 k-pair rows x 32 c of f16x2, stride 40
    // (bank = (8j + c) & 31, bijective per access group -> conflict-free).
    // Reused (stride 36 words) for the f32 D transpose (8m x 32c: 288 < 320).
    __shared__ uint32_t s_gf[8][8 * 40];

    const int warp = threadIdx.x >> 5;
    const int lane = threadIdx.x & 31;
    const int point = blockIdx.x * 8 + warp;       // grid covers 160000 exactly
    uint32_t* sg = s_gf[warp];

    // ---- neighbor indices: warp-uniform broadcast LDG.128 x4 ----
    const int4* ip = (const int4*)(inds + (size_t)point * 16);
    const int4 i0 = __ldg(ip + 0);
    const int4 i1 = __ldg(ip + 1);
    const int4 i2 = __ldg(ip + 2);
    const int4 i3 = __ldg(ip + 3);

    // ---- B operand (weights) loads issued early ----
    // b0: w[k=2(lane&3)][m=lane>>2], k+1; b1: k+8, k+9. word(k,m) = 8k + m.
    const float* wp = wn + (size_t)point * 128;
    const int wbase = 16 * (lane & 3) + (lane >> 2);
    const float w0 = __ldg(wp + wbase);
    const float w1 = __ldg(wp + wbase + 8);
    const float w2 = __ldg(wp + wbase + 64);
    const float w3 = __ldg(wp + wbase + 72);

    // ---- guidance, coalesced: lane j holds guid[point*64 + j] ----
    // G[k][h] = guid[4k+h]. Pre-pack P[j][h] = (G[2j][h], G[2j+1][h]) as f16x2,
    // resident at lane 8j+h (partner = lane+4).
    const float g0 = __ldg(guid + point * 64 + lane);
    const float g1 = __ldg(guid + point * 64 + 32 + lane);
    const uint32_t gpackA = pack_f16x2(g0, __shfl_xor_sync(FULLMASK, g0, 4));
    const uint32_t gpackB = pack_f16x2(g1, __shfl_xor_sync(FULLMASK, g1, 4));
    const int hsel = lane >> 3;                     // head of this lane's channel

    const float* fb = feat + ((point >= NPERB) ? NPERB * 32 : 0);

    // ---- gather + guidance multiply (f32) + f16 pack + stage:
    //      sg[j][c] = half2(gf[2j][c], gf[2j+1][c]) ----
#define GF_PAIR(j, idxA, idxB, gpack)                                          \
    do {                                                                       \
        const float fa = __ldg(fb + (idxA) * 32 + lane);                       \
        const float fbv = __ldg(fb + (idxB) * 32 + lane);                      \
        const uint32_t gp = __shfl_sync(FULLMASK, (gpack), 8 * ((j) & 3) + hsel); \
        const float2 gv = unpack_f16x2(gp);                                    \
        sg[(j) * 40 + lane] = pack_f16x2(fa * gv.x, fbv * gv.y);               \
    } while (0)

    GF_PAIR(0, i0.x, i0.y, gpackA);
    GF_PAIR(1, i0.z, i0.w, gpackA);
    GF_PAIR(2, i1.x, i1.y, gpackA);
    GF_PAIR(3, i1.z, i1.w, gpackA);
    GF_PAIR(4, i2.x, i2.y, gpackB);
    GF_PAIR(5, i2.z, i2.w, gpackB);
    GF_PAIR(6, i3.x, i3.y, gpackB);
    GF_PAIR(7, i3.z, i3.w, gpackB);
#undef GF_PAIR
    __syncwarp();

    // ---- B fragments: pack 4 f32 weights into 2 f16x2 regs ----
    const uint32_t B0 = pack_f16x2(w0, w1);   // k = 2(lane&3), +1
    const uint32_t B1 = pack_f16x2(w2, w3);   // k = 2(lane&3)+8, +9

    // ---- 2 M-tiles (t = c-halves), K=16 in one mma each ----
    float d[2][4];
    const int j0 = lane & 3;
    #pragma unroll
    for (int t = 0; t < 2; t++) {
        #pragma unroll
        for (int i = 0; i < 4; i++) d[t][i] = 0.0f;
        // A frags: a0:(c=c0, j=j0)  a1:(c0+8)  a2:(j0+4)  a3:(c0+8, j0+4)
        const int c0 = (lane >> 2) + 16 * t;
        uint32_t A[4];
        A[0] = sg[j0 * 40 + c0];
        A[1] = sg[j0 * 40 + c0 + 8];
        A[2] = sg[(j0 + 4) * 40 + c0];
        A[3] = sg[(j0 + 4) * 40 + c0 + 8];
        mma16(d[t], A, B0, B1);
    }
    __syncwarp();   // all A-frag reads complete before sg is overwritten

    // ---- D -> smem transpose (stride 36: bank = (4m + c)&31 pattern is
    //      bijective per access group -> conflict-free) ----
    // d[t]: d0:(c=c0, m=m0)  d1:(c0, m0+1)  d2:(c0+8, m0)  d3:(c0+8, m0+1)
    #pragma unroll
    for (int t = 0; t < 2; t++) {
        const int c0 = (lane >> 2) + 16 * t;
        const int m0 = 2 * (lane & 3);
        sg[m0 * 36 + c0]            = __float_as_uint(d[t][0]);
        sg[(m0 + 1) * 36 + c0]      = __float_as_uint(d[t][1]);
        sg[m0 * 36 + c0 + 8]        = __float_as_uint(d[t][2]);
        sg[(m0 + 1) * 36 + c0 + 8]  = __float_as_uint(d[t][3]);
    }
    __syncwarp();

    // ---- coalesced store: out[point, m*32 + c], 1 wf per row ----
    float* op = out + (size_t)point * 256;
    #pragma unroll
    for (int m = 0; m < 8; m++)
        op[m * 32 + lane] = __uint_as_float(sg[m * 36 + lane]);
}

extern "C" void kernel_launch(void* const* d_in, const int* in_sizes, int n_in,
                              void* d_out, int out_size) {
    const float* feat = (const float*)d_in[0];   // [B,N,C]
    const int*   inds = (const int*)  d_in[1];   // [B,N,K]
    const float* guid = (const float*)d_in[2];   // [B,N,K,H]
    const float* wn   = (const float*)d_in[3];   // [B,N,K,M]
    float* out = (float*)d_out;                  // [B,N,M*C]

    pconv_hmma<<<20000, 256>>>(feat, inds, guid, wn, out);
}